// round 11
// baseline (speedup 1.0000x reference)
#include <cuda_runtime.h>
#include <cuda_bf16.h>

#define BQ      16
#define LSEQ    2048
#define DH      64
#define CHUNK   128
#define NC      (LSEQ/CHUNK)    // 16
#define SSTR    2056            // packed-P row stride (words)
#define QSTR    72              // phase-1 bf16 row stride (elements)
#define VSTR    40              // phase-3 bf16 row stride (elements)
#define RSTR    20              // reduction scratch row stride (floats)
#define NBH     64
#define THREADS 512

#define WSTAGE  5120
// smem: S(packed P) + Qhi/Qlo + 16 warp stage regions + 2 reduction buffers
#define SMEM_BYTES (BQ*SSTR*4 + 2*BQ*QSTR*2 + 16*WSTAGE + 2*16*RSTR*4)  // 220672

// ---- global bf16 hi/lo planes for K and V (filled by pre-pass kernel) ----
__device__ __nv_bfloat16 gKhi[NBH*LSEQ*DH];
__device__ __nv_bfloat16 gKlo[NBH*LSEQ*DH];
__device__ __nv_bfloat16 gVhi[NBH*LSEQ*DH];
__device__ __nv_bfloat16 gVlo[NBH*LSEQ*DH];

__device__ __forceinline__ unsigned short bits(__nv_bfloat16 h) {
    return *reinterpret_cast<unsigned short*>(&h);
}

__device__ __forceinline__ void split4(float4 v, uint2& hi, uint2& lo) {
    __nv_bfloat16 h0 = __float2bfloat16_rn(v.x);
    __nv_bfloat16 h1 = __float2bfloat16_rn(v.y);
    __nv_bfloat16 h2 = __float2bfloat16_rn(v.z);
    __nv_bfloat16 h3 = __float2bfloat16_rn(v.w);
    __nv_bfloat16 l0 = __float2bfloat16_rn(v.x - __bfloat162float(h0));
    __nv_bfloat16 l1 = __float2bfloat16_rn(v.y - __bfloat162float(h1));
    __nv_bfloat16 l2 = __float2bfloat16_rn(v.z - __bfloat162float(h2));
    __nv_bfloat16 l3 = __float2bfloat16_rn(v.w - __bfloat162float(h3));
    hi.x = (unsigned)bits(h0) | ((unsigned)bits(h1) << 16);
    hi.y = (unsigned)bits(h2) | ((unsigned)bits(h3) << 16);
    lo.x = (unsigned)bits(l0) | ((unsigned)bits(l1) << 16);
    lo.y = (unsigned)bits(l2) | ((unsigned)bits(l3) << 16);
}

// pack one fp32 -> (hi bf16) | (lo bf16)<<16
__device__ __forceinline__ unsigned pack1(float x) {
    __nv_bfloat16 h = __float2bfloat16_rn(x);
    __nv_bfloat16 l = __float2bfloat16_rn(x - __bfloat162float(h));
    return (unsigned)bits(h) | ((unsigned)bits(l) << 16);
}

__device__ __forceinline__ void mma16816(float* d, const unsigned* a,
                                         unsigned b0, unsigned b1) {
    asm volatile(
        "mma.sync.aligned.m16n8k16.row.col.f32.bf16.bf16.f32 "
        "{%0,%1,%2,%3}, {%4,%5,%6,%7}, {%8,%9}, {%0,%1,%2,%3};"
        : "+f"(d[0]), "+f"(d[1]), "+f"(d[2]), "+f"(d[3])
        : "r"(a[0]), "r"(a[1]), "r"(a[2]), "r"(a[3]), "r"(b0), "r"(b1));
}

__device__ __forceinline__ void ldsm4(unsigned* r, const void* p) {
    unsigned addr = (unsigned)__cvta_generic_to_shared(p);
    asm volatile(
        "ldmatrix.sync.aligned.m8n8.x4.shared.b16 {%0,%1,%2,%3}, [%4];"
        : "=r"(r[0]), "=r"(r[1]), "=r"(r[2]), "=r"(r[3]) : "r"(addr));
}

__device__ __forceinline__ void ldsm4t(unsigned* r, const void* p) {
    unsigned addr = (unsigned)__cvta_generic_to_shared(p);
    asm volatile(
        "ldmatrix.sync.aligned.m8n8.x4.trans.shared.b16 {%0,%1,%2,%3}, [%4];"
        : "=r"(r[0]), "=r"(r[1]), "=r"(r[2]), "=r"(r[3]) : "r"(addr));
}

__device__ __forceinline__ void cp16(void* dst, const void* src) {
    unsigned d = (unsigned)__cvta_generic_to_shared(dst);
    asm volatile("cp.async.cg.shared.global [%0], [%1], 16;" :: "r"(d), "l"(src));
}
__device__ __forceinline__ void cp_commit() { asm volatile("cp.async.commit_group;"); }
__device__ __forceinline__ void cp_wait1()  { asm volatile("cp.async.wait_group 1;"); }
__device__ __forceinline__ void cp_wait0()  { asm volatile("cp.async.wait_group 0;"); }

// ==================== pre-pass: split K,V into bf16 hi/lo planes ====================
__global__ __launch_bounds__(256)
void convert_kv(const float4* __restrict__ K, const float4* __restrict__ V)
{
    int i = blockIdx.x * blockDim.x + threadIdx.x;
    uint2 hi, lo;
    float4 k = K[i];
    split4(k, hi, lo);
    ((uint2*)gKhi)[i] = hi; ((uint2*)gKlo)[i] = lo;
    float4 v = V[i];
    split4(v, hi, lo);
    ((uint2*)gVhi)[i] = hi; ((uint2*)gVlo)[i] = lo;
}

// ==================== main kernel ====================
__global__ __launch_bounds__(THREADS, 1)
void sdpa_kernel(const float* __restrict__ Qg, float* __restrict__ ctx,
                 float* __restrict__ attn)
{
    extern __shared__ float sm[];
    float*          S    = sm;                                   // packed P: 16 x 2056 words
    __nv_bfloat16*  Qhi  = (__nv_bfloat16*)(S + BQ * SSTR);      // 16 x 72
    __nv_bfloat16*  Qlo  = Qhi + BQ * QSTR;
    char*           StageBase = (char*)(Qlo + BQ * QSTR);        // 16 x WSTAGE
    float*          red1 = (float*)(StageBase + 16 * WSTAGE);    // 16 x RSTR
    float*          red2 = red1 + 16 * RSTR;                     // 16 x RSTR

    const int tid  = threadIdx.x;
    const int bh   = blockIdx.y;
    const int qt   = blockIdx.x;
    const long qbase = ((long)bh * LSEQ + (long)qt * BQ) * DH;
    const long kvoff = (long)bh * LSEQ * DH;

    const int warp = tid >> 5;      // 0..15
    const int lane = tid & 31;
    const int g    = lane >> 2;     // 0..7
    const int tg   = lane & 3;      // 0..3

    char* wreg = StageBase + warp * WSTAGE;   // this warp's private stage region

    auto stageK = [&](int buf, int chunk) {
        __nv_bfloat16* bh_ = (__nv_bfloat16*)(wreg + buf * 2304);
        __nv_bfloat16* bl_ = (__nv_bfloat16*)(wreg + buf * 2304 + 1152);
        const long gofs = kvoff + (long)(chunk * CHUNK + warp * 8) * DH;
        #pragma unroll
        for (int p = 0; p < 2; ++p) {
            int idx = lane + p * 32;
            int row = idx >> 3, c8 = (idx & 7) << 3;
            cp16(&bh_[row * QSTR + c8], &gKhi[gofs + (long)row * DH + c8]);
            cp16(&bl_[row * QSTR + c8], &gKlo[gofs + (long)row * DH + c8]);
        }
        cp_commit();
    };

    const int seg   = warp & 7;     // phase-3: 16-key segment
    const int dhalf = warp >> 3;    // phase-3: 32-dim half

    auto stageV = [&](int buf, int chunk) {
        __nv_bfloat16* bh_ = (__nv_bfloat16*)(wreg + buf * 2560);
        __nv_bfloat16* bl_ = (__nv_bfloat16*)(wreg + buf * 2560 + 1280);
        const long gofs = kvoff + (long)(chunk * CHUNK + seg * 16) * DH + dhalf * 32;
        #pragma unroll
        for (int p = 0; p < 2; ++p) {
            int idx = lane + p * 32;
            int row = idx >> 2, c8 = (idx & 3) << 3;
            cp16(&bh_[row * VSTR + c8], &gVhi[gofs + (long)row * DH + c8]);
            cp16(&bl_[row * VSTR + c8], &gVlo[gofs + (long)row * DH + c8]);
        }
        cp_commit();
    };

    // ---- stage Q (first 256 threads) + K chunk 0 ----
    if (tid < 256) {
        int r  = tid >> 4;
        int d4 = (tid & 15) << 2;
        float4 v = *(const float4*)&Qg[qbase + (long)r * DH + d4];
        uint2 hi, lo; split4(v, hi, lo);
        *(uint2*)&Qhi[r * QSTR + d4] = hi;
        *(uint2*)&Qlo[r * QSTR + d4] = lo;
    }
    stageK(0, 0);
    __syncthreads();    // Q planes visible

    // ---- hoist Q fragments ----
    unsigned qh[4][4], ql[4][4];
    #pragma unroll
    for (int ks = 0; ks < 4; ++ks) {
        const int ko = ks * 16;
        qh[ks][0] = *(unsigned*)&Qhi[ g      * QSTR + ko + tg*2    ];
        qh[ks][1] = *(unsigned*)&Qhi[(g + 8) * QSTR + ko + tg*2    ];
        qh[ks][2] = *(unsigned*)&Qhi[ g      * QSTR + ko + tg*2 + 8];
        qh[ks][3] = *(unsigned*)&Qhi[(g + 8) * QSTR + ko + tg*2 + 8];
        ql[ks][0] = *(unsigned*)&Qlo[ g      * QSTR + ko + tg*2    ];
        ql[ks][1] = *(unsigned*)&Qlo[(g + 8) * QSTR + ko + tg*2    ];
        ql[ks][2] = *(unsigned*)&Qlo[ g      * QSTR + ko + tg*2 + 8];
        ql[ks][3] = *(unsigned*)&Qlo[(g + 8) * QSTR + ko + tg*2 + 8];
    }

    // ==================== Phase 1: scores -> registers (no S store) ====================
    // s[c][0..1] = row g, cols warp*8+tg*2(+1); s[c][2..3] = row g+8
    float s[NC][4];
    {
        const int lr = lane & 7;
        const int cg = (lane >> 3) * 8;

        #pragma unroll
        for (int c = 0; c < NC; ++c) {
            if (c + 1 < NC) { stageK((c + 1) & 1, c + 1); cp_wait1(); }
            else            { cp_wait0(); }

            const __nv_bfloat16* KhiB = (const __nv_bfloat16*)(wreg + (c & 1) * 2304);
            const __nv_bfloat16* KloB = (const __nv_bfloat16*)(wreg + (c & 1) * 2304 + 1152);

            unsigned kh[2][4], kl[2][4];
            ldsm4(kh[0], &KhiB[lr * QSTR +  0 + cg]);
            ldsm4(kh[1], &KhiB[lr * QSTR + 32 + cg]);
            ldsm4(kl[0], &KloB[lr * QSTR +  0 + cg]);
            ldsm4(kl[1], &KloB[lr * QSTR + 32 + cg]);

            float a0[4] = {}, a1[4] = {}, a2[4] = {};
            #pragma unroll
            for (int ks = 0; ks < 4; ++ks) {
                const unsigned* bb = &kh[ks >> 1][(ks & 1) * 2];
                const unsigned* bl = &kl[ks >> 1][(ks & 1) * 2];
                mma16816(a0, qh[ks], bb[0], bb[1]);
                mma16816(a1, qh[ks], bl[0], bl[1]);
                mma16816(a2, ql[ks], bb[0], bb[1]);
            }
            #pragma unroll
            for (int i = 0; i < 4; ++i) s[c][i] = a0[i] + a1[i] + a2[i];
        }
    }

    // stage V chunk 0 now — hidden behind the whole softmax
    stageV(0, 0);

    // ==================== Phase 2: softmax entirely in registers ====================
    float mG = -1e30f, m8 = -1e30f;
    #pragma unroll
    for (int c = 0; c < NC; ++c) {
        mG = fmaxf(mG, fmaxf(s[c][0], s[c][1]));
        m8 = fmaxf(m8, fmaxf(s[c][2], s[c][3]));
    }
    // quad reduce (cols within quad)
    mG = fmaxf(mG, __shfl_xor_sync(0xffffffffu, mG, 1));
    mG = fmaxf(mG, __shfl_xor_sync(0xffffffffu, mG, 2));
    m8 = fmaxf(m8, __shfl_xor_sync(0xffffffffu, m8, 1));
    m8 = fmaxf(m8, __shfl_xor_sync(0xffffffffu, m8, 2));
    if (tg == 0) {
        red1[ g      * RSTR + warp] = mG;
        red1[(g + 8) * RSTR + warp] = m8;
    }
    __syncthreads();
    {
        float4 a = *(float4*)&red1[ g * RSTR + 0];
        float4 b = *(float4*)&red1[ g * RSTR + 4];
        float4 cc= *(float4*)&red1[ g * RSTR + 8];
        float4 d = *(float4*)&red1[ g * RSTR + 12];
        mG = fmaxf(fmaxf(fmaxf(a.x,a.y),fmaxf(a.z,a.w)),
             fmaxf(fmaxf(fmaxf(b.x,b.y),fmaxf(b.z,b.w)),
             fmaxf(fmaxf(fmaxf(cc.x,cc.y),fmaxf(cc.z,cc.w)),
                   fmaxf(fmaxf(d.x,d.y),fmaxf(d.z,d.w)))));
        a = *(float4*)&red1[(g+8) * RSTR + 0];
        b = *(float4*)&red1[(g+8) * RSTR + 4];
        cc= *(float4*)&red1[(g+8) * RSTR + 8];
        d = *(float4*)&red1[(g+8) * RSTR + 12];
        m8 = fmaxf(fmaxf(fmaxf(a.x,a.y),fmaxf(a.z,a.w)),
             fmaxf(fmaxf(fmaxf(b.x,b.y),fmaxf(b.z,b.w)),
             fmaxf(fmaxf(fmaxf(cc.x,cc.y),fmaxf(cc.z,cc.w)),
                   fmaxf(fmaxf(d.x,d.y),fmaxf(d.z,d.w)))));
    }

    float sG = 0.f, s8 = 0.f;
    #pragma unroll
    for (int c = 0; c < NC; ++c) {
        s[c][0] = __expf(s[c][0] - mG);
        s[c][1] = __expf(s[c][1] - mG);
        s[c][2] = __expf(s[c][2] - m8);
        s[c][3] = __expf(s[c][3] - m8);
        sG += s[c][0] + s[c][1];
        s8 += s[c][2] + s[c][3];
    }
    sG += __shfl_xor_sync(0xffffffffu, sG, 1);
    sG += __shfl_xor_sync(0xffffffffu, sG, 2);
    s8 += __shfl_xor_sync(0xffffffffu, s8, 1);
    s8 += __shfl_xor_sync(0xffffffffu, s8, 2);
    if (tg == 0) {
        red2[ g      * RSTR + warp] = sG;
        red2[(g + 8) * RSTR + warp] = s8;
    }
    __syncthreads();
    {
        float4 a = *(float4*)&red2[ g * RSTR + 0];
        float4 b = *(float4*)&red2[ g * RSTR + 4];
        float4 cc= *(float4*)&red2[ g * RSTR + 8];
        float4 d = *(float4*)&red2[ g * RSTR + 12];
        sG = (a.x+a.y+a.z+a.w) + (b.x+b.y+b.z+b.w)
           + (cc.x+cc.y+cc.z+cc.w) + (d.x+d.y+d.z+d.w);
        a = *(float4*)&red2[(g+8) * RSTR + 0];
        b = *(float4*)&red2[(g+8) * RSTR + 4];
        cc= *(float4*)&red2[(g+8) * RSTR + 8];
        d = *(float4*)&red2[(g+8) * RSTR + 12];
        s8 = (a.x+a.y+a.z+a.w) + (b.x+b.y+b.z+b.w)
           + (cc.x+cc.y+cc.z+cc.w) + (d.x+d.y+d.z+d.w);
    }
    const float invG = 1.0f / sG;
    const float inv8 = 1.0f / s8;

    // ---- scale; write attn straight from regs; pack P into S smem ----
    {
        const long arowG = ((long)bh * LSEQ + (long)qt * BQ + g     ) * LSEQ;
        const long arow8 = ((long)bh * LSEQ + (long)qt * BQ + g + 8 ) * LSEQ;
        #pragma unroll
        for (int c = 0; c < NC; ++c) {
            const int col = c * CHUNK + warp * 8 + tg * 2;
            float2 pg = make_float2(s[c][0] * invG, s[c][1] * invG);
            float2 p8 = make_float2(s[c][2] * inv8, s[c][3] * inv8);
            *(float2*)&attn[arowG + col] = pg;
            *(float2*)&attn[arow8 + col] = p8;
            *(uint2*)&S[ g      * SSTR + col] = make_uint2(pack1(pg.x), pack1(pg.y));
            *(uint2*)&S[(g + 8) * SSTR + col] = make_uint2(pack1(p8.x), pack1(p8.y));
        }
    }
    __syncthreads();    // packed P visible to all warps

    // ==================== Phase 3: ctx = P @ V  (barrier-free chunk loop) ====================
    float acc[4][4] = {};
    {
        const int kb   = seg * 16;
        const int lrow = lane & 15;
        const int lcol = (lane >> 4) * 8;

        for (int c = 0; c < NC; ++c) {
            if (c + 1 < NC) { stageV((c + 1) & 1, c + 1); cp_wait1(); }
            else            { cp_wait0(); }

            const __nv_bfloat16* VhiB = (const __nv_bfloat16*)(wreg + (c & 1) * 2560);
            const __nv_bfloat16* VloB = (const __nv_bfloat16*)(wreg + (c & 1) * 2560 + 1280);

            const int col = c * CHUNK + kb;
            uint2 w0 = *(uint2*)&S[ g      * SSTR + col + tg*2    ];
            uint2 w1 = *(uint2*)&S[(g + 8) * SSTR + col + tg*2    ];
            uint2 w2 = *(uint2*)&S[ g      * SSTR + col + tg*2 + 8];
            uint2 w3 = *(uint2*)&S[(g + 8) * SSTR + col + tg*2 + 8];
            unsigned ah[4], al[4];
            ah[0] = __byte_perm(w0.x, w0.y, 0x5410); al[0] = __byte_perm(w0.x, w0.y, 0x7632);
            ah[1] = __byte_perm(w1.x, w1.y, 0x5410); al[1] = __byte_perm(w1.x, w1.y, 0x7632);
            ah[2] = __byte_perm(w2.x, w2.y, 0x5410); al[2] = __byte_perm(w2.x, w2.y, 0x7632);
            ah[3] = __byte_perm(w3.x, w3.y, 0x5410); al[3] = __byte_perm(w3.x, w3.y, 0x7632);

            #pragma unroll
            for (int p = 0; p < 2; ++p) {
                const int d0 = p * 16;
                unsigned hb[4], lb[4];
                ldsm4t(hb, &VhiB[lrow * VSTR + d0 + lcol]);
                ldsm4t(lb, &VloB[lrow * VSTR + d0 + lcol]);
                mma16816(acc[2*p    ], ah, hb[0], hb[1]);
                mma16816(acc[2*p + 1], ah, hb[2], hb[3]);
                mma16816(acc[2*p    ], ah, lb[0], lb[1]);
                mma16816(acc[2*p + 1], ah, lb[2], lb[3]);
                mma16816(acc[2*p    ], al, hb[0], hb[1]);
                mma16816(acc[2*p + 1], al, hb[2], hb[3]);
            }
        }
    }

    // ---- cross-warp reduction: 8 segments x 2 dim-halves ----
    __syncthreads();
    float* scr = (float*)StageBase;          // 16 slots x 16 rows x 36 stride
    {
        const int slot = dhalf * 8 + seg;
        #pragma unroll
        for (int nt = 0; nt < 4; ++nt) {
            const int d2 = nt * 8 + tg * 2;
            *(float2*)&scr[slot * 576 +  g      * 36 + d2] = make_float2(acc[nt][0], acc[nt][1]);
            *(float2*)&scr[slot * 576 + (g + 8) * 36 + d2] = make_float2(acc[nt][2], acc[nt][3]);
        }
    }
    __syncthreads();

    {
        const int row = tid >> 5;                // 0..15
        const int dc  = (tid & 31) << 1;         // 0..62
        const int base = (dc < 32) ? 0 : 8;
        const int dl   = dc & 31;
        float2 sv = {0.f, 0.f};
        #pragma unroll
        for (int w = 0; w < 8; ++w) {
            float2 v = *(float2*)&scr[(base + w) * 576 + row * 36 + dl];
            sv.x += v.x; sv.y += v.y;
        }
        *(float2*)&ctx[qbase + (long)row * DH + dc] = sv;
    }
}

extern "C" void kernel_launch(void* const* d_in, const int* in_sizes, int n_in,
                              void* d_out, int out_size)
{
    const float* Q = (const float*)d_in[0];
    const float* K = (const float*)d_in[1];
    const float* V = (const float*)d_in[2];

    float* ctx  = (float*)d_out;                         // [B,H,L,D]
    float* attn = ctx + (size_t)NBH * LSEQ * DH;         // [B,H,L,L]

    convert_kv<<<(NBH*LSEQ*DH/4 + 255)/256, 256>>>((const float4*)K, (const float4*)V);

    cudaFuncSetAttribute(sdpa_kernel,
                         cudaFuncAttributeMaxDynamicSharedMemorySize, SMEM_BYTES);

    dim3 grid(LSEQ / BQ, NBH);
    sdpa_kernel<<<grid, THREADS, SMEM_BYTES>>>(Q, ctx, attn);
}